// round 3
// baseline (speedup 1.0000x reference)
#include <cuda_runtime.h>
#include <cuda_bf16.h>
#include <mma.h>
#include <cstdint>

using namespace nvcuda;

// Problem constants
#define NDIM 256
#define NN   65536        // 256*256 elements per matrix
#define BATCH 8192
#define TSTEPS 16
#define KBIG  4096        // T * N

// Workspace slot map (each slot = one 256x256 fp32 matrix):
//  0        : U1
//  1..15    : P_k = U2^k
//  16,17,18 : U1^2, U1^4, U1^8
//  19       : W2
//  20       : W1
//  21       : Wo
//  22..37   : Q[s]  = W2 @ U2^(15-s)
//  38..53   : V ping
//  54..69   : V pong
//  70..85   : D[s]  = W1 @ C_s
//  86..101  : A[s]  (contiguous -> the [4096,256] stacked matrix for the big GEMM)
#define NMAT 102
__device__ float g_mat[(size_t)NMAT * NN];

struct MMItem { int a, b, c, add; };   // a==-1 -> copy add->c ; add==-1 -> no add
struct MMArgs { MMItem it[16]; };

__device__ __forceinline__ float to_tf32(float x) {
    uint32_t r;
    asm("cvt.rna.tf32.f32 %0, %1;" : "=r"(r) : "f"(x));
    return __uint_as_float(r);
}

// ---------------------------------------------------------------------------
// Copy the 5 weight matrices into workspace slots (and W2 -> Q[15]).
// ---------------------------------------------------------------------------
__global__ void __launch_bounds__(256) copy_inputs(
    const float* __restrict__ W1, const float* __restrict__ U1,
    const float* __restrict__ W2, const float* __restrict__ U2,
    const float* __restrict__ Wo)
{
    int i = blockIdx.x * blockDim.x + threadIdx.x;
    if (i < NN) {
        g_mat[(size_t)0  * NN + i] = U1[i];
        g_mat[(size_t)1  * NN + i] = U2[i];   // P_1
        g_mat[(size_t)19 * NN + i] = W2[i];
        g_mat[(size_t)20 * NN + i] = W1[i];
        g_mat[(size_t)21 * NN + i] = Wo[i];
        g_mat[(size_t)37 * NN + i] = W2[i];   // Q[15] = W2 @ U2^0
    }
}

// ---------------------------------------------------------------------------
// Batched 256x256x256 matmul: C = A @ B (+ ADD), split-tf32 (hi/lo, 3 MMA
// passes) so chained products keep ~fp32 accuracy.
// Grid: (4, 4, nitems); CTA computes a 64x64 tile. 256 threads = 8 warps,
// each warp owns a 16x32 strip (2 wmma accumulators).
// ---------------------------------------------------------------------------
__global__ void __launch_bounds__(256) mm_small(MMArgs args)
{
    const MMItem it = args.it[blockIdx.z];
    const int row0 = blockIdx.y * 64;
    const int col0 = blockIdx.x * 64;
    const int tid = threadIdx.x;
    float* C = g_mat + (size_t)it.c * NN;

    if (it.a < 0) {  // pure copy
        const float* S = g_mat + (size_t)it.add * NN;
        for (int i = tid; i < 64 * 64; i += 256) {
            int r = i >> 6, c = i & 63;
            C[(row0 + r) * NDIM + col0 + c] = S[(row0 + r) * NDIM + col0 + c];
        }
        return;
    }

    const float* A  = g_mat + (size_t)it.a * NN;
    const float* Bm = g_mat + (size_t)it.b * NN;

    __shared__ float sAh[64 * 32], sAl[64 * 32];
    __shared__ float sBh[32 * 64], sBl[32 * 64];
    __shared__ float sC[64 * 64];

    wmma::fragment<wmma::accumulator, 16, 16, 8, float> acc[2];
    wmma::fill_fragment(acc[0], 0.0f);
    wmma::fill_fragment(acc[1], 0.0f);

    const int wid = tid >> 5;
    const int wr  = wid & 3;   // 0..3 -> row block of 16
    const int wc  = wid >> 2;  // 0..1 -> col block of 32

    for (int kc = 0; kc < NDIM; kc += 32) {
        for (int i = tid; i < 64 * 32; i += 256) {
            int r = i >> 5, c = i & 31;
            float v = A[(row0 + r) * NDIM + kc + c];
            float h = to_tf32(v);
            sAh[i] = h;
            sAl[i] = to_tf32(v - h);
        }
        for (int i = tid; i < 32 * 64; i += 256) {
            int r = i >> 6, c = i & 63;
            float v = Bm[(kc + r) * NDIM + col0 + c];
            float h = to_tf32(v);
            sBh[i] = h;
            sBl[i] = to_tf32(v - h);
        }
        __syncthreads();

        #pragma unroll
        for (int ks = 0; ks < 4; ks++) {
            wmma::fragment<wmma::matrix_a, 16, 16, 8, wmma::precision::tf32, wmma::row_major> ah, al;
            wmma::load_matrix_sync(ah, sAh + (wr * 16) * 32 + ks * 8, 32);
            wmma::load_matrix_sync(al, sAl + (wr * 16) * 32 + ks * 8, 32);
            #pragma unroll
            for (int cb = 0; cb < 2; cb++) {
                wmma::fragment<wmma::matrix_b, 16, 16, 8, wmma::precision::tf32, wmma::row_major> bh, bl;
                wmma::load_matrix_sync(bh, sBh + (ks * 8) * 64 + wc * 32 + cb * 16, 64);
                wmma::load_matrix_sync(bl, sBl + (ks * 8) * 64 + wc * 32 + cb * 16, 64);
                wmma::mma_sync(acc[cb], ah, bh, acc[cb]);
                wmma::mma_sync(acc[cb], ah, bl, acc[cb]);
                wmma::mma_sync(acc[cb], al, bh, acc[cb]);
            }
        }
        __syncthreads();
    }

    wmma::store_matrix_sync(sC + (wr * 16) * 64 + wc * 32,      acc[0], 64, wmma::mem_row_major);
    wmma::store_matrix_sync(sC + (wr * 16) * 64 + wc * 32 + 16, acc[1], 64, wmma::mem_row_major);
    __syncthreads();

    const float* ADD = (it.add >= 0) ? (g_mat + (size_t)it.add * NN) : nullptr;
    for (int i = tid; i < 64 * 64; i += 256) {
        int r = i >> 6, c = i & 63;
        float v = sC[i];
        if (ADD) v += ADD[(row0 + r) * NDIM + col0 + c];
        C[(row0 + r) * NDIM + col0 + c] = v;
    }
}

// ---------------------------------------------------------------------------
// Main GEMM: out[8192,256] = X[8192,4096] @ ABIG[4096,256], single-pass tf32.
// Grid (2, 64); CTA tile 128x128, 8 warps, each warp 32x64 (2x4 accumulators).
// ---------------------------------------------------------------------------
__global__ void __launch_bounds__(256) main_gemm(
    const float* __restrict__ X, float* __restrict__ out)
{
    const float* Bm = g_mat + (size_t)86 * NN;  // [4096, 256] row-major
    const int row0 = blockIdx.y * 128;
    const int col0 = blockIdx.x * 128;
    const int tid = threadIdx.x;
    const int wid = tid >> 5;
    const int wr  = wid & 3;   // row block of 32
    const int wc  = wid >> 2;  // col block of 64

    __shared__ float sA[128 * 32];
    __shared__ float sB[32 * 128];

    wmma::fragment<wmma::accumulator, 16, 16, 8, float> acc[2][4];
    #pragma unroll
    for (int i = 0; i < 2; i++)
        #pragma unroll
        for (int j = 0; j < 4; j++)
            wmma::fill_fragment(acc[i][j], 0.0f);

    for (int kc = 0; kc < KBIG; kc += 32) {
        // A tile: 128x32 (float4 vectorized, coalesced)
        for (int i = tid * 4; i < 128 * 32; i += 256 * 4) {
            int r = i >> 5, c = i & 31;
            float4 v = *reinterpret_cast<const float4*>(&X[(size_t)(row0 + r) * KBIG + kc + c]);
            sA[i + 0] = to_tf32(v.x);
            sA[i + 1] = to_tf32(v.y);
            sA[i + 2] = to_tf32(v.z);
            sA[i + 3] = to_tf32(v.w);
        }
        // B tile: 32x128
        for (int i = tid * 4; i < 32 * 128; i += 256 * 4) {
            int r = i >> 7, c = i & 127;
            float4 v = *reinterpret_cast<const float4*>(&Bm[(kc + r) * NDIM + col0 + c]);
            sB[i + 0] = to_tf32(v.x);
            sB[i + 1] = to_tf32(v.y);
            sB[i + 2] = to_tf32(v.z);
            sB[i + 3] = to_tf32(v.w);
        }
        __syncthreads();

        #pragma unroll
        for (int ks = 0; ks < 4; ks++) {
            wmma::fragment<wmma::matrix_a, 16, 16, 8, wmma::precision::tf32, wmma::row_major> a[2];
            #pragma unroll
            for (int i = 0; i < 2; i++)
                wmma::load_matrix_sync(a[i], sA + (wr * 32 + i * 16) * 32 + ks * 8, 32);
            wmma::fragment<wmma::matrix_b, 16, 16, 8, wmma::precision::tf32, wmma::row_major> b[4];
            #pragma unroll
            for (int j = 0; j < 4; j++)
                wmma::load_matrix_sync(b[j], sB + (ks * 8) * 128 + wc * 64 + j * 16, 128);
            #pragma unroll
            for (int i = 0; i < 2; i++)
                #pragma unroll
                for (int j = 0; j < 4; j++)
                    wmma::mma_sync(acc[i][j], a[i], b[j], acc[i][j]);
        }
        __syncthreads();
    }

    #pragma unroll
    for (int i = 0; i < 2; i++)
        #pragma unroll
        for (int j = 0; j < 4; j++)
            wmma::store_matrix_sync(
                out + (size_t)(row0 + wr * 32 + i * 16) * NDIM + col0 + wc * 64 + j * 16,
                acc[i][j], NDIM, wmma::mem_row_major);
}

// ---------------------------------------------------------------------------
// Host side
// ---------------------------------------------------------------------------
static inline void run_mm(const MMItem* items, int n) {
    MMArgs a;
    for (int i = 0; i < n; i++) a.it[i] = items[i];
    mm_small<<<dim3(4, 4, n), 256>>>(a);
}

extern "C" void kernel_launch(void* const* d_in, const int* in_sizes, int n_in,
                              void* d_out, int out_size)
{
    const float* x  = (const float*)d_in[0];
    const float* W1 = (const float*)d_in[1];
    const float* U1 = (const float*)d_in[2];
    const float* W2 = (const float*)d_in[3];
    const float* U2 = (const float*)d_in[4];
    const float* Wo = (const float*)d_in[5];
    float* out = (float*)d_out;
    (void)in_sizes; (void)n_in; (void)out_size;

    copy_inputs<<<256, 256>>>(W1, U1, W2, U2, Wo);

    // Powers of U2 (P_k, slots 1..15) and U1^{2,4,8} (16,17,18), log depth.
    { MMItem m[] = {{1,1,2,-1},{0,0,16,-1}};                               run_mm(m, 2); }
    { MMItem m[] = {{2,1,3,-1},{2,2,4,-1},{16,16,17,-1}};                  run_mm(m, 3); }
    { MMItem m[] = {{4,1,5,-1},{4,2,6,-1},{4,3,7,-1},{4,4,8,-1},
                    {17,17,18,-1}};                                        run_mm(m, 5); }
    { MMItem m[] = {{8,1,9,-1},{8,2,10,-1},{8,3,11,-1},{8,4,12,-1},
                    {8,5,13,-1},{8,6,14,-1},{8,7,15,-1}};                  run_mm(m, 7); }

    // Q[s] = W2 @ U2^(15-s), s=0..14  (Q[15]=W2 already copied)
    { MMItem m[16];
      for (int s = 0; s < 15; s++) m[s] = {19, 15 - s, 22 + s, -1};
      run_mm(m, 15); }

    // Hillis-Steele scan: C_s = sum_{u>=s} U1^(u-s) @ Q[u]
    // level 0: Vping[s] = U1 @ Q[s+1] + Q[s]
    { MMItem m[16];
      for (int s = 0; s < 15; s++) m[s] = {0, 23 + s, 38 + s, 22 + s};
      m[15] = {-1, 0, 53, 37};
      run_mm(m, 16); }
    // level 1: Vpong[s] = U1^2 @ Vping[s+2] + Vping[s]
    { MMItem m[16];
      for (int s = 0; s < 14; s++) m[s] = {16, 40 + s, 54 + s, 38 + s};
      for (int s = 14; s < 16; s++) m[s] = {-1, 0, 54 + s, 38 + s};
      run_mm(m, 16); }
    // level 2: Vping[s] = U1^4 @ Vpong[s+4] + Vpong[s]
    { MMItem m[16];
      for (int s = 0; s < 12; s++) m[s] = {17, 58 + s, 38 + s, 54 + s};
      for (int s = 12; s < 16; s++) m[s] = {-1, 0, 38 + s, 54 + s};
      run_mm(m, 16); }
    // level 3: Vpong[s] = U1^8 @ Vping[s+8] + Vping[s]  -> C_s in slots 54+s
    { MMItem m[16];
      for (int s = 0; s < 8; s++)  m[s] = {18, 46 + s, 54 + s, 38 + s};
      for (int s = 8; s < 16; s++) m[s] = {-1, 0, 54 + s, 38 + s};
      run_mm(m, 16); }

    // D[s] = W1 @ C_s
    { MMItem m[16];
      for (int s = 0; s < 16; s++) m[s] = {20, 54 + s, 70 + s, -1};
      run_mm(m, 16); }
    // A[s] = D[s] @ Wo  (slots 86..101 = contiguous [4096,256] matrix)
    { MMItem m[16];
      for (int s = 0; s < 16; s++) m[s] = {70 + s, 21, 86 + s, -1};
      run_mm(m, 16); }

    // out = X_flat[8192,4096] @ ABIG[4096,256]
    main_gemm<<<dim3(2, 64), 256>>>(x, out);
}

// round 4
// speedup vs baseline: 1.9480x; 1.9480x over previous
#include <cuda_runtime.h>
#include <cuda_bf16.h>
#include <mma.h>
#include <cstdint>

using namespace nvcuda;

// Problem constants
#define NDIM 256
#define NN   65536        // 256*256 elements per matrix
#define KBIG 4096         // T * N

// Workspace slot map (each slot = one 256x256 fp32 matrix):
//  0:U1  1..15:U2^k  16,17,18:U1^2,4,8  19:W2  20:W1  21:Wo
//  22..37:Q[s]  38..53:V ping  54..69:V pong  70..85:D[s]  86..101:A[s]
#define NMAT 102
__device__ float g_mat[(size_t)NMAT * NN];

struct MMItem { int a, b, c, add; };   // a==-1 -> copy add->c ; add==-1 -> no add
struct MMArgs { MMItem it[16]; };

__device__ __forceinline__ float to_tf32(float x) {
    uint32_t r;
    asm("cvt.rna.tf32.f32 %0, %1;" : "=r"(r) : "f"(x));
    return __uint_as_float(r);
}

#define SPLIT_STORE4(dsth, dstl, v4) do {                                   \
    float _h;                                                               \
    _h = to_tf32((v4).x); (dsth)[0] = _h; (dstl)[0] = to_tf32((v4).x - _h); \
    _h = to_tf32((v4).y); (dsth)[1] = _h; (dstl)[1] = to_tf32((v4).y - _h); \
    _h = to_tf32((v4).z); (dsth)[2] = _h; (dstl)[2] = to_tf32((v4).z - _h); \
    _h = to_tf32((v4).w); (dsth)[3] = _h; (dstl)[3] = to_tf32((v4).w - _h); \
} while (0)

#define CVT_STORE4(dst, v4) do {      \
    (dst)[0] = to_tf32((v4).x);       \
    (dst)[1] = to_tf32((v4).y);       \
    (dst)[2] = to_tf32((v4).z);       \
    (dst)[3] = to_tf32((v4).w);       \
} while (0)

// ---------------------------------------------------------------------------
// Copy the 5 weight matrices into workspace slots (and W2 -> Q[15]).
// ---------------------------------------------------------------------------
__global__ void __launch_bounds__(256) copy_inputs(
    const float* __restrict__ W1, const float* __restrict__ U1,
    const float* __restrict__ W2, const float* __restrict__ U2,
    const float* __restrict__ Wo)
{
    int i = blockIdx.x * blockDim.x + threadIdx.x;
    if (i < NN) {
        g_mat[(size_t)0  * NN + i] = U1[i];
        g_mat[(size_t)1  * NN + i] = U2[i];   // P_1
        g_mat[(size_t)19 * NN + i] = W2[i];
        g_mat[(size_t)20 * NN + i] = W1[i];
        g_mat[(size_t)21 * NN + i] = Wo[i];
        g_mat[(size_t)37 * NN + i] = W2[i];   // Q[15] = W2 @ U2^0
    }
}

// ---------------------------------------------------------------------------
// Batched 256x256x256 matmul: C = A @ B (+ ADD), split-tf32 (3 MMA passes).
// Grid (4, 2, nitems): CTA tile = 128 rows x 64 cols. 8 warps (4x2),
// warp tile 32x32 (2x2 fp32 accumulators). Padded smem, register prefetch.
// ADD is fused by preloading accumulator fragments straight from gmem.
// ---------------------------------------------------------------------------
#define SA_LD 20
#define SB_LD 68

__global__ void __launch_bounds__(256) mm_small(MMArgs args)
{
    const MMItem it = args.it[blockIdx.z];
    const int row0 = blockIdx.y * 128;
    const int col0 = blockIdx.x * 64;
    const int tid  = threadIdx.x;
    float* C = g_mat + (size_t)it.c * NN;

    if (it.a < 0) {  // pure copy of a 128x64 tile (2048 float4)
        const float* S = g_mat + (size_t)it.add * NN;
        #pragma unroll
        for (int i = 0; i < 8; i++) {
            int idx = tid + i * 256;
            int r = idx >> 4, c = (idx & 15) << 2;
            *reinterpret_cast<float4*>(&C[(size_t)(row0 + r) * NDIM + col0 + c]) =
                *reinterpret_cast<const float4*>(&S[(size_t)(row0 + r) * NDIM + col0 + c]);
        }
        return;
    }

    const float* A  = g_mat + (size_t)it.a * NN;
    const float* Bm = g_mat + (size_t)it.b * NN;

    __shared__ float sAh[128 * SA_LD], sAl[128 * SA_LD];
    __shared__ float sBh[16 * SB_LD],  sBl[16 * SB_LD];

    const int wid = tid >> 5;
    const int wr  = wid & 3;   // 4 row-warps of 32
    const int wc  = wid >> 2;  // 2 col-warps of 32

    wmma::fragment<wmma::accumulator, 16, 16, 8, float> acc[2][2];
    if (it.add >= 0) {
        const float* ADD = g_mat + (size_t)it.add * NN;
        #pragma unroll
        for (int i = 0; i < 2; i++)
            #pragma unroll
            for (int j = 0; j < 2; j++)
                wmma::load_matrix_sync(acc[i][j],
                    ADD + (size_t)(row0 + wr * 32 + i * 16) * NDIM + col0 + wc * 32 + j * 16,
                    NDIM, wmma::mem_row_major);
    } else {
        #pragma unroll
        for (int i = 0; i < 2; i++)
            #pragma unroll
            for (int j = 0; j < 2; j++)
                wmma::fill_fragment(acc[i][j], 0.0f);
    }

    // Per-thread gmem->reg prefetch slots: A tile 128x16 (2 float4/thr),
    // B tile 16x64 (1 float4/thr)
    const int la0 = tid * 4;
    const int la1 = la0 + 1024;
    const int ra0 = la0 >> 4, ca0 = la0 & 15;
    const int ra1 = la1 >> 4, ca1 = la1 & 15;
    const int rb0 = la0 >> 6, cb0 = la0 & 63;

    float4 pa0 = *reinterpret_cast<const float4*>(&A[(size_t)(row0 + ra0) * NDIM + ca0]);
    float4 pa1 = *reinterpret_cast<const float4*>(&A[(size_t)(row0 + ra1) * NDIM + ca1]);
    float4 pb0 = *reinterpret_cast<const float4*>(&Bm[(size_t)rb0 * NDIM + col0 + cb0]);

    #pragma unroll 1
    for (int kc = 0; kc < 16; kc++) {
        SPLIT_STORE4(&sAh[ra0 * SA_LD + ca0], &sAl[ra0 * SA_LD + ca0], pa0);
        SPLIT_STORE4(&sAh[ra1 * SA_LD + ca1], &sAl[ra1 * SA_LD + ca1], pa1);
        SPLIT_STORE4(&sBh[rb0 * SB_LD + cb0], &sBl[rb0 * SB_LD + cb0], pb0);
        __syncthreads();

        if (kc < 15) {
            int k0 = (kc + 1) * 16;
            pa0 = *reinterpret_cast<const float4*>(&A[(size_t)(row0 + ra0) * NDIM + k0 + ca0]);
            pa1 = *reinterpret_cast<const float4*>(&A[(size_t)(row0 + ra1) * NDIM + k0 + ca1]);
            pb0 = *reinterpret_cast<const float4*>(&Bm[(size_t)(k0 + rb0) * NDIM + col0 + cb0]);
        }

        #pragma unroll
        for (int ks = 0; ks < 2; ks++) {
            wmma::fragment<wmma::matrix_a, 16, 16, 8, wmma::precision::tf32, wmma::row_major> ah[2], al[2];
            #pragma unroll
            for (int i = 0; i < 2; i++) {
                wmma::load_matrix_sync(ah[i], &sAh[(wr * 32 + i * 16) * SA_LD + ks * 8], SA_LD);
                wmma::load_matrix_sync(al[i], &sAl[(wr * 32 + i * 16) * SA_LD + ks * 8], SA_LD);
            }
            wmma::fragment<wmma::matrix_b, 16, 16, 8, wmma::precision::tf32, wmma::row_major> bh[2], bl[2];
            #pragma unroll
            for (int j = 0; j < 2; j++) {
                wmma::load_matrix_sync(bh[j], &sBh[(ks * 8) * SB_LD + wc * 32 + j * 16], SB_LD);
                wmma::load_matrix_sync(bl[j], &sBl[(ks * 8) * SB_LD + wc * 32 + j * 16], SB_LD);
            }
            #pragma unroll
            for (int i = 0; i < 2; i++)
                #pragma unroll
                for (int j = 0; j < 2; j++) {
                    wmma::mma_sync(acc[i][j], ah[i], bh[j], acc[i][j]);
                    wmma::mma_sync(acc[i][j], ah[i], bl[j], acc[i][j]);
                    wmma::mma_sync(acc[i][j], al[i], bh[j], acc[i][j]);
                }
        }
        if (kc < 15) __syncthreads();
    }

    #pragma unroll
    for (int i = 0; i < 2; i++)
        #pragma unroll
        for (int j = 0; j < 2; j++)
            wmma::store_matrix_sync(
                C + (size_t)(row0 + wr * 32 + i * 16) * NDIM + col0 + wc * 32 + j * 16,
                acc[i][j], NDIM, wmma::mem_row_major);
}

// ---------------------------------------------------------------------------
// Main GEMM: out[8192,256] = X[8192,4096] @ ABIG[4096,256], single-pass tf32.
// Grid (2, 64): CTA tile 128x128. 8 warps (4x2), warp tile 32x64 (2x4 accums).
// Padded smem (36/136), register-prefetch double buffering, KC=32.
// ---------------------------------------------------------------------------
#define MA_LD 36
#define MB_LD 136

__global__ void __launch_bounds__(256) main_gemm(
    const float* __restrict__ X, float* __restrict__ out)
{
    const float* Bm = g_mat + (size_t)86 * NN;  // [4096, 256] row-major
    const int row0 = blockIdx.y * 128;
    const int col0 = blockIdx.x * 128;
    const int tid  = threadIdx.x;
    const int wid  = tid >> 5;
    const int wr   = wid & 3;   // 4 row-warps of 32
    const int wc   = wid >> 2;  // 2 col-warps of 64

    __shared__ float sA[128 * MA_LD];
    __shared__ float sB[32 * MB_LD];

    wmma::fragment<wmma::accumulator, 16, 16, 8, float> acc[2][4];
    #pragma unroll
    for (int i = 0; i < 2; i++)
        #pragma unroll
        for (int j = 0; j < 4; j++)
            wmma::fill_fragment(acc[i][j], 0.0f);

    // Per-thread prefetch: A tile 128x32 -> 4 float4, B tile 32x128 -> 4 float4
    int raA[4], caA[4], raB[4], caB[4];
    #pragma unroll
    for (int q = 0; q < 4; q++) {
        int la = tid * 4 + q * 1024;
        raA[q] = la >> 5;  caA[q] = la & 31;
        raB[q] = la >> 7;  caB[q] = la & 127;
    }

    float4 pa[4], pb[4];
    #pragma unroll
    for (int q = 0; q < 4; q++) {
        pa[q] = *reinterpret_cast<const float4*>(&X[(size_t)(row0 + raA[q]) * KBIG + caA[q]]);
        pb[q] = *reinterpret_cast<const float4*>(&Bm[(size_t)raB[q] * NDIM + col0 + caB[q]]);
    }

    #pragma unroll 1
    for (int kc = 0; kc < 128; kc++) {
        #pragma unroll
        for (int q = 0; q < 4; q++) {
            CVT_STORE4(&sA[raA[q] * MA_LD + caA[q]], pa[q]);
            CVT_STORE4(&sB[raB[q] * MB_LD + caB[q]], pb[q]);
        }
        __syncthreads();

        if (kc < 127) {
            int k0 = (kc + 1) * 32;
            #pragma unroll
            for (int q = 0; q < 4; q++) {
                pa[q] = *reinterpret_cast<const float4*>(&X[(size_t)(row0 + raA[q]) * KBIG + k0 + caA[q]]);
                pb[q] = *reinterpret_cast<const float4*>(&Bm[(size_t)(k0 + raB[q]) * NDIM + col0 + caB[q]]);
            }
        }

        #pragma unroll
        for (int ks = 0; ks < 4; ks++) {
            wmma::fragment<wmma::matrix_a, 16, 16, 8, wmma::precision::tf32, wmma::row_major> a[2];
            #pragma unroll
            for (int i = 0; i < 2; i++)
                wmma::load_matrix_sync(a[i], &sA[(wr * 32 + i * 16) * MA_LD + ks * 8], MA_LD);
            wmma::fragment<wmma::matrix_b, 16, 16, 8, wmma::precision::tf32, wmma::row_major> b[4];
            #pragma unroll
            for (int j = 0; j < 4; j++)
                wmma::load_matrix_sync(b[j], &sB[(ks * 8) * MB_LD + wc * 64 + j * 16], MB_LD);
            #pragma unroll
            for (int i = 0; i < 2; i++)
                #pragma unroll
                for (int j = 0; j < 4; j++)
                    wmma::mma_sync(acc[i][j], a[i], b[j], acc[i][j]);
        }
        if (kc < 127) __syncthreads();
    }

    #pragma unroll
    for (int i = 0; i < 2; i++)
        #pragma unroll
        for (int j = 0; j < 4; j++)
            wmma::store_matrix_sync(
                out + (size_t)(row0 + wr * 32 + i * 16) * NDIM + col0 + wc * 64 + j * 16,
                acc[i][j], NDIM, wmma::mem_row_major);
}

// ---------------------------------------------------------------------------
// Host side
// ---------------------------------------------------------------------------
static inline void run_mm(const MMItem* items, int n) {
    MMArgs a;
    for (int i = 0; i < n; i++) a.it[i] = items[i];
    mm_small<<<dim3(4, 2, n), 256>>>(a);
}

extern "C" void kernel_launch(void* const* d_in, const int* in_sizes, int n_in,
                              void* d_out, int out_size)
{
    const float* x  = (const float*)d_in[0];
    const float* W1 = (const float*)d_in[1];
    const float* U1 = (const float*)d_in[2];
    const float* W2 = (const float*)d_in[3];
    const float* U2 = (const float*)d_in[4];
    const float* Wo = (const float*)d_in[5];
    float* out = (float*)d_out;
    (void)in_sizes; (void)n_in; (void)out_size;

    copy_inputs<<<256, 256>>>(W1, U1, W2, U2, Wo);

    // Powers of U2 (slots 1..15) and U1^{2,4,8} (16,17,18), log depth.
    { MMItem m[] = {{1,1,2,-1},{0,0,16,-1}};                               run_mm(m, 2); }
    { MMItem m[] = {{2,1,3,-1},{2,2,4,-1},{16,16,17,-1}};                  run_mm(m, 3); }
    { MMItem m[] = {{4,1,5,-1},{4,2,6,-1},{4,3,7,-1},{4,4,8,-1},
                    {17,17,18,-1}};                                        run_mm(m, 5); }
    { MMItem m[] = {{8,1,9,-1},{8,2,10,-1},{8,3,11,-1},{8,4,12,-1},
                    {8,5,13,-1},{8,6,14,-1},{8,7,15,-1}};                  run_mm(m, 7); }

    // Q[s] = W2 @ U2^(15-s), s=0..14  (Q[15]=W2 already copied)
    { MMItem m[16];
      for (int s = 0; s < 15; s++) m[s] = {19, 15 - s, 22 + s, -1};
      run_mm(m, 15); }

    // Hillis-Steele scan: C_s = sum_{u>=s} U1^(u-s) @ Q[u]
    { MMItem m[16];
      for (int s = 0; s < 15; s++) m[s] = {0, 23 + s, 38 + s, 22 + s};
      m[15] = {-1, 0, 53, 37};
      run_mm(m, 16); }
    { MMItem m[16];
      for (int s = 0; s < 14; s++) m[s] = {16, 40 + s, 54 + s, 38 + s};
      for (int s = 14; s < 16; s++) m[s] = {-1, 0, 54 + s, 38 + s};
      run_mm(m, 16); }
    { MMItem m[16];
      for (int s = 0; s < 12; s++) m[s] = {17, 58 + s, 38 + s, 54 + s};
      for (int s = 12; s < 16; s++) m[s] = {-1, 0, 38 + s, 54 + s};
      run_mm(m, 16); }
    { MMItem m[16];
      for (int s = 0; s < 8; s++)  m[s] = {18, 46 + s, 54 + s, 38 + s};
      for (int s = 8; s < 16; s++) m[s] = {-1, 0, 54 + s, 38 + s};
      run_mm(m, 16); }

    // D[s] = W1 @ C_s
    { MMItem m[16];
      for (int s = 0; s < 16; s++) m[s] = {20, 54 + s, 70 + s, -1};
      run_mm(m, 16); }
    // A[s] = D[s] @ Wo  (slots 86..101 = contiguous [4096,256] matrix)
    { MMItem m[16];
      for (int s = 0; s < 16; s++) m[s] = {70 + s, 21, 86 + s, -1};
      run_mm(m, 16); }

    // out = X_flat[8192,4096] @ ABIG[4096,256]
    main_gemm<<<dim3(2, 64), 256>>>(x, out);
}